// round 16
// baseline (speedup 1.0000x reference)
#include <cuda_runtime.h>
#include <cuda_fp16.h>
#include <math.h>
#include <stdint.h>

#define BB   4
#define TT   1024
#define CC   1024
#define HH   16
#define DD   64
#define BT   (BB*TT)          // 4096

// Scratch (allocation-free rule: __device__ globals)
__device__ __half g_Qh[BT * CC];
__device__ __half g_Kh[BT * CC];
__device__ __half g_Vh[BT * CC];
__device__ __half g_Yh[BT * CC];
__device__ __half g_Xh[BT * CC];          // fp16-rounded x
__device__ __half g_Wh[4 * CC * CC];      // fp16-rounded Wq|Wk|Wv|Wp
__device__ __half g_P[(size_t)BB * HH * TT * TT];   // fp16 attention probs

// ---------------------------------------------------------------------------
// helpers
// ---------------------------------------------------------------------------
__device__ __forceinline__ uint2 f4_to_h4(float4 v) {
    __half2 a = __floats2half2_rn(v.x, v.y);
    __half2 b = __floats2half2_rn(v.z, v.w);
    uint2 r;
    r.x = *(uint32_t*)&a;
    r.y = *(uint32_t*)&b;
    return r;
}

__device__ __forceinline__ void mma_f16(float* c, const uint32_t* a, const uint32_t* b) {
    asm volatile(
        "mma.sync.aligned.m16n8k16.row.col.f32.f16.f16.f32 "
        "{%0,%1,%2,%3}, {%4,%5,%6,%7}, {%8,%9}, {%0,%1,%2,%3};"
        : "+f"(c[0]), "+f"(c[1]), "+f"(c[2]), "+f"(c[3])
        : "r"(a[0]), "r"(a[1]), "r"(a[2]), "r"(a[3]), "r"(b[0]), "r"(b[1]));
}

__device__ __forceinline__ void ldsm_x4(uint32_t& r0, uint32_t& r1,
                                        uint32_t& r2, uint32_t& r3, uint32_t addr) {
    asm volatile("ldmatrix.sync.aligned.m8n8.x4.shared.b16 {%0,%1,%2,%3}, [%4];"
                 : "=r"(r0), "=r"(r1), "=r"(r2), "=r"(r3) : "r"(addr));
}
__device__ __forceinline__ void ldsm_x4t(uint32_t& r0, uint32_t& r1,
                                         uint32_t& r2, uint32_t& r3, uint32_t addr) {
    asm volatile("ldmatrix.sync.aligned.m8n8.x4.trans.shared.b16 {%0,%1,%2,%3}, [%4];"
                 : "=r"(r0), "=r"(r1), "=r"(r2), "=r"(r3) : "r"(addr));
}

// streaming stores (write-through, no L2 allocate) for never-re-read outputs
__device__ __forceinline__ void stwt_f4(float* p, float4 v) {
    asm volatile("st.global.wt.v4.f32 [%0], {%1,%2,%3,%4};"
                 :: "l"(p), "f"(v.x), "f"(v.y), "f"(v.z), "f"(v.w) : "memory");
}
__device__ __forceinline__ void stwt_f2(float* p, float2 v) {
    asm volatile("st.global.wt.v2.f32 [%0], {%1,%2};"
                 :: "l"(p), "f"(v.x), "f"(v.y) : "memory");
}
__device__ __forceinline__ void stwt_u1(__half* p, uint32_t v) {
    asm volatile("st.global.wt.u32 [%0], %1;"
                 :: "l"(p), "r"(v) : "memory");
}

#define CPA16(dst_u32, src_ptr) \
    asm volatile("cp.async.cg.shared.global [%0], [%1], 16;" \
                 :: "r"(dst_u32), "l"(src_ptr))
#define CPCOMMIT() asm volatile("cp.async.commit_group;")
#define CPWAIT(n)  asm volatile("cp.async.wait_group %0;" :: "n"(n))

// ---------------------------------------------------------------------------
// prepass: fp16-round x -> g_Xh, weights -> g_Wh (concat)
// ---------------------------------------------------------------------------
__global__ void prepass(const float* __restrict__ x,
                        const float* __restrict__ wq, const float* __restrict__ wk,
                        const float* __restrict__ wv, const float* __restrict__ wp)
{
    int which = blockIdx.y;
    const float* src;
    __half* dst;
    int n4;
    if (which == 0) { src = x;  dst = g_Xh; n4 = BT * CC / 4; }
    else {
        src = (which == 1) ? wq : (which == 2) ? wk : (which == 3) ? wv : wp;
        dst = g_Wh + (size_t)(which - 1) * CC * CC;
        n4 = CC * CC / 4;
    }
    for (int i = blockIdx.x * blockDim.x + threadIdx.x; i < n4;
         i += gridDim.x * blockDim.x) {
        float4 v = ((const float4*)src)[i];
        ((uint2*)dst)[i] = f4_to_h4(v);
    }
}

// ---------------------------------------------------------------------------
// C[M,N] = A[M,K] @ W[N,K]^T, FP16 MMA m16n8k16, inputs pre-rounded fp16.
// 128x128 tile, BK=32, 512 threads, 4-stage cp.async, ldmatrix fragments.
// (R7/R10 configuration — known good.)
// ---------------------------------------------------------------------------
#define AST 40                   // halfs per row (80 bytes)
#define GSTG (128 * AST * 2)     // stage bytes per array: 10240
#define NTG 32                   // K/32
__global__ __launch_bounds__(512, 1)
void gemm_f16_nt(const __half* __restrict__ A, const __half* __restrict__ Wb,
                 __half* __restrict__ H0, __half* __restrict__ H1,
                 __half* __restrict__ H2, float* __restrict__ C0, int ro)
{
    const __half* Bw = Wb + (size_t)blockIdx.z * CC * CC;
    __half* H = (blockIdx.z == 0) ? H0 : (blockIdx.z == 1 ? H1 : H2);

    extern __shared__ char smraw[];
    uint32_t sAu = (uint32_t)__cvta_generic_to_shared(smraw);
    uint32_t sBu = sAu + 4 * GSTG;

    const int tid  = threadIdx.x;
    const int lane = tid & 31;
    const int warp = tid >> 5;
    const int wm   = (warp & 3) * 32;
    const int wn   = (warp >> 2) * 32;

    const int lrow = lane & 15;
    const int lkof = (lane & 16) ? 8 : 0;     // halfs
    const uint32_t aoff0 = ((wm + lrow)      * AST + lkof) * 2;
    const uint32_t aoff1 = ((wm + 16 + lrow) * AST + lkof) * 2;
    const uint32_t boff0 = ((wn + lrow)      * AST + lkof) * 2;
    const uint32_t boff1 = ((wn + 16 + lrow) * AST + lkof) * 2;

    const __half* Abase = A  + (size_t)(blockIdx.y * 128) * CC;
    const __half* Bbase = Bw + (size_t)(blockIdx.x * 128) * CC;

    auto load_stage = [&](int kt, int s) {
        int row = tid >> 2, seg = tid & 3;               // 512 granules per array
        CPA16(sAu + s * GSTG + row * 80 + seg * 16,
              Abase + (size_t)row * CC + kt * 32 + seg * 8);
        CPA16(sBu + s * GSTG + row * 80 + seg * 16,
              Bbase + (size_t)row * CC + kt * 32 + seg * 8);
        CPCOMMIT();
    };

    load_stage(0, 0);
    load_stage(1, 1);
    load_stage(2, 2);

    float acc[2][4][4];
    #pragma unroll
    for (int i = 0; i < 2; i++)
        #pragma unroll
        for (int j = 0; j < 4; j++)
            #pragma unroll
            for (int k = 0; k < 4; k++) acc[i][j][k] = 0.f;

    for (int kt = 0; kt < NTG; kt++) {
        if (kt <= NTG - 3)      { CPWAIT(2); }
        else if (kt == NTG - 2) { CPWAIT(1); }
        else                    { CPWAIT(0); }
        __syncthreads();

        if (kt + 3 < NTG) load_stage(kt + 3, (kt + 3) & 3);

        const uint32_t AbU = sAu + (kt & 3) * GSTG;
        const uint32_t BbU = sBu + (kt & 3) * GSTG;

        #pragma unroll
        for (int ks = 0; ks < 2; ks++) {                 // 2 x k16
            uint32_t af[2][4], bf[4][2];
            ldsm_x4(af[0][0], af[0][1], af[0][2], af[0][3], AbU + aoff0 + ks * 32);
            ldsm_x4(af[1][0], af[1][1], af[1][2], af[1][3], AbU + aoff1 + ks * 32);
            ldsm_x4(bf[0][0], bf[1][0], bf[0][1], bf[1][1], BbU + boff0 + ks * 32);
            ldsm_x4(bf[2][0], bf[3][0], bf[2][1], bf[3][1], BbU + boff1 + ks * 32);
            #pragma unroll
            for (int mt = 0; mt < 2; mt++)
                #pragma unroll
                for (int nt = 0; nt < 4; nt++)
                    mma_f16(acc[mt][nt], af[mt], bf[nt]);
        }
    }

    #pragma unroll
    for (int mt = 0; mt < 2; mt++) {
        int r0 = blockIdx.y * 128 + wm + mt * 16 + (lane >> 2);
        #pragma unroll
        for (int nt = 0; nt < 4; nt++) {
            int c0 = blockIdx.x * 128 + wn + nt * 8 + (lane & 3) * 2;
            if (ro) {
                __half2 h01 = __floats2half2_rn(acc[mt][nt][0], acc[mt][nt][1]);
                __half2 h23 = __floats2half2_rn(acc[mt][nt][2], acc[mt][nt][3]);
                *(__half2*)&H[(size_t)r0 * CC + c0]       = h01;
                *(__half2*)&H[(size_t)(r0 + 8) * CC + c0] = h23;
            } else {
                stwt_f2(&C0[(size_t)r0 * CC + c0],
                        make_float2(acc[mt][nt][0], acc[mt][nt][1]));
                stwt_f2(&C0[(size_t)(r0 + 8) * CC + c0],
                        make_float2(acc[mt][nt][2], acc[mt][nt][3]));
            }
        }
    }
}

// ---------------------------------------------------------------------------
// Kernel A: two-pass strip-free scores + ALiBi + online softmax.
// block=(b,h,64q), 256 thr, occ 2, smem 84.5KB (Q + 4-deep K ring + stats).
// Pass 1 (cc 0..7): QK chunks, online (max, rescaled exp-sum) per row.
// cc==8: combine lane/warp partials -> per-row (M, 1/sum).
// Pass 2 (cc 8..15): recompute chunks (bit-identical MMAs), write normalized
// attn fp32 + P fp16 directly from fragments (streaming stores).
// K traffic per (b,h): 2 passes x 16 CTAs x 128KB -> half of QT=16 scheme.
// ---------------------------------------------------------------------------
#define QT   64
#define QST  72
#define KST  72
#define KCH  (128 * KST * 2)     // 18432 bytes per K chunk buffer
__global__ __launch_bounds__(256, 2)
void attn_score_kernel(const __half* __restrict__ Q, const __half* __restrict__ Km,
                       float* __restrict__ attn, __half* __restrict__ Ph)
{
    extern __shared__ char smraw[];
    __half* sQ = (__half*)smraw;                           // 64*72 halfs (9216B)
    char*   sK = smraw + QT * QST * 2;                     // 4 * KCH (73728B)
    float2* sStat = (float2*)(smraw + QT * QST * 2 + 4 * KCH);   // [2][64]
    float2* sFin  = sStat + 2 * 64;                               // [64]
    uint32_t sQu = (uint32_t)__cvta_generic_to_shared(sQ);
    uint32_t sKu = (uint32_t)__cvta_generic_to_shared(sK);

    const int tid  = threadIdx.x;
    const int lane = tid & 31;
    const int warp = tid >> 5;            // 0..7
    const int qb   = blockIdx.x * QT;
    const int h    = blockIdx.y;
    const int b    = blockIdx.z;

    const float scale = 0.125f;
    const float slope = exp2f(-0.5f * (float)(h + 1));

    const int mt   = warp >> 1;           // m16 tile (rows mt*16..+15)
    const int nhalf = warp & 1;           // n64 half of the 128-col chunk

    const int lrow = lane & 15;
    const int lkof = (lane & 16) ? 8 : 0;

    const __half* Kb = Km + ((size_t)(b * TT)) * CC + h * DD;

    auto issueK = [&](int c, int buf) {
        const __half* base = Kb + (size_t)(c * 128) * CC;
        #pragma unroll
        for (int i = 0; i < 4; i++) {
            int g = tid + i * 256;              // 1024 granules
            int row = g >> 3, seg = g & 7;
            CPA16(sKu + buf * KCH + row * (KST * 2) + seg * 16,
                  base + (size_t)row * CC + seg * 8);
        }
        CPCOMMIT();
    };

    issueK(0, 0);
    issueK(1, 1);
    issueK(2, 2);

    // Q tile [64 x 64] halfs -> sQ
    {
        const __half* Qb = Q + ((size_t)(b * TT + qb)) * CC + h * DD;
        #pragma unroll
        for (int i = 0; i < 2; i++) {
            int g = tid + i * 256;              // 512 granules
            int row = g >> 3, seg = g & 7;
            *(uint4*)(sQ + row * QST + seg * 8) =
                *(const uint4*)(Qb + (size_t)row * CC + seg * 8);
        }
    }
    __syncthreads();

    // hoist Q fragments (this warp's m16 tile, all 4 k16 steps)
    uint32_t aq[4][4];
    {
        uint32_t qoff = sQu + ((mt * 16 + lrow) * QST + lkof) * 2;
        #pragma unroll
        for (int ks = 0; ks < 4; ks++)
            ldsm_x4(aq[ks][0], aq[ks][1], aq[ks][2], aq[ks][3], qoff + ks * 32);
    }

    uint32_t koffj[4];
    #pragma unroll
    for (int j = 0; j < 4; j++)
        koffj[j] = ((nhalf * 64 + j * 16 + lrow) * KST + lkof) * 2;

    float mrow[2] = {-1e30f, -1e30f};
    float srow[2] = {0.f, 0.f};
    float Mrow[2], Ivrow[2];

    const size_t attn_base = (((size_t)(b * HH + h)) * TT + qb) * TT;
    const int r0 = mt * 16 + (lane >> 2);
    const float q0f = (float)(qb + r0);

    for (int cc = 0; cc < 16; cc++) {
        if (cc <= 13)      { CPWAIT(2); }
        else if (cc == 14) { CPWAIT(1); }
        else               { CPWAIT(0); }
        __syncthreads();

        if (cc + 3 < 16) issueK((cc + 3) & 7, (cc + 3) & 3);

        if (cc == 8) {
            // finalize pass-1 stats: reduce over the 4-lane col group
            #pragma unroll
            for (int ri = 0; ri < 2; ri++) {
                float m = mrow[ri], s = srow[ri];
                #pragma unroll
                for (int off = 1; off <= 2; off <<= 1) {
                    float mo = __shfl_xor_sync(~0u, m, off);
                    float so = __shfl_xor_sync(~0u, s, off);
                    float mn = fmaxf(m, mo);
                    s = s * __expf(m - mn) + so * __expf(mo - mn);
                    m = mn;
                }
                mrow[ri] = m; srow[ri] = s;
            }
            if ((lane & 3) == 0) {
                sStat[nhalf * 64 + r0]     = make_float2(mrow[0], srow[0]);
                sStat[nhalf * 64 + r0 + 8] = make_float2(mrow[1], srow[1]);
            }
            __syncthreads();
            if (tid < 64) {
                float2 a = sStat[tid], c2 = sStat[64 + tid];
                float M = fmaxf(a.x, c2.x);
                float sum = a.y * __expf(a.x - M) + c2.y * __expf(c2.x - M);
                sFin[tid] = make_float2(M, 1.0f / sum);
            }
            __syncthreads();
            float2 f0 = sFin[r0], f1 = sFin[r0 + 8];
            Mrow[0] = f0.x; Ivrow[0] = f0.y;
            Mrow[1] = f1.x; Ivrow[1] = f1.y;
        }

        const int chunk = cc & 7;
        const uint32_t KU = sKu + (cc & 3) * KCH;

        float cr[8][4];
        #pragma unroll
        for (int nt = 0; nt < 8; nt++)
            #pragma unroll
            for (int i = 0; i < 4; i++) cr[nt][i] = 0.f;

        #pragma unroll
        for (int ks = 0; ks < 4; ks++) {
            uint32_t bf[8][2];
            #pragma unroll
            for (int j = 0; j < 4; j++)
                ldsm_x4(bf[2 * j][0], bf[2 * j + 1][0],
                        bf[2 * j][1], bf[2 * j + 1][1], KU + koffj[j] + ks * 32);
            #pragma unroll
            for (int nt = 0; nt < 8; nt++)
                mma_f16(cr[nt], aq[ks], bf[nt]);
        }

        // in-place: MMA result -> ALiBi score
        const int kc = chunk * 128;
        #pragma unroll
        for (int nt = 0; nt < 8; nt++) {
            #pragma unroll
            for (int i = 0; i < 4; i++) {
                float qf = q0f + (float)((i >> 1) * 8);
                float kf = (float)(kc + nhalf * 64 + nt * 8 + (lane & 3) * 2 + (i & 1));
                cr[nt][i] = cr[nt][i] * scale - slope * fabsf(qf - kf);
            }
        }

        if (cc < 8) {
            // pass 1: online max + rescaled exp-sum per row
            #pragma unroll
            for (int ri = 0; ri < 2; ri++) {
                float vmax = -1e30f;
                #pragma unroll
                for (int nt = 0; nt < 8; nt++)
                    vmax = fmaxf(vmax, fmaxf(cr[nt][ri * 2], cr[nt][ri * 2 + 1]));
                float mn = fmaxf(mrow[ri], vmax);
                float acc = 0.f;
                #pragma unroll
                for (int nt = 0; nt < 8; nt++)
                    acc += __expf(cr[nt][ri * 2] - mn) + __expf(cr[nt][ri * 2 + 1] - mn);
                srow[ri] = srow[ri] * __expf(mrow[ri] - mn) + acc;
                mrow[ri] = mn;
            }
        } else {
            // pass 2: normalize + stream out attn fp32 and P fp16
            #pragma unroll
            for (int ri = 0; ri < 2; ri++) {
                int r = r0 + ri * 8;
                float*  orow = attn + attn_base + (size_t)r * TT;
                __half* prow = Ph + attn_base + (size_t)r * TT;
                #pragma unroll
                for (int nt = 0; nt < 8; nt++) {
                    float p0 = __expf(cr[nt][ri * 2]     - Mrow[ri]) * Ivrow[ri];
                    float p1 = __expf(cr[nt][ri * 2 + 1] - Mrow[ri]) * Ivrow[ri];
                    int col = kc + nhalf * 64 + nt * 8 + (lane & 3) * 2;
                    stwt_f2(orow + col, make_float2(p0, p1));
                    __half2 hp = __floats2half2_rn(p0, p1);
                    stwt_u1(prow + col, *(uint32_t*)&hp);
                }
            }
        }
    }
}

// ---------------------------------------------------------------------------
// Kernel B: Y[128x64] = P[128x1024] @ V[1024x64] per (b,h,qtile), all fp16.
// 256 thr, 4-stage cp.async, P via ldmatrix, V via ldmatrix.trans.
// (R10 configuration — known good.)
// ---------------------------------------------------------------------------
#define PST 40
#define VST 72
#define PSTGB (128 * PST * 2)     // 10240
#define VSTGB (32 * VST * 2)      // 4608
__global__ __launch_bounds__(256, 2)
void pv_kernel(const __half* __restrict__ Ph, const __half* __restrict__ V,
               __half* __restrict__ Y)
{
    extern __shared__ char smraw[];
    uint32_t sPu = (uint32_t)__cvta_generic_to_shared(smraw);
    uint32_t sVu = sPu + 4 * PSTGB;

    const int tid  = threadIdx.x;
    const int lane = tid & 31;
    const int warp = tid >> 5;            // 0..7
    const int qb   = blockIdx.x * 128;
    const int h    = blockIdx.y;
    const int b    = blockIdx.z;

    const int wm = (warp >> 1) * 32;
    const int wn = (warp & 1) * 32;

    const int lrow = lane & 15;
    const int lkof = (lane & 16) ? 8 : 0;
    const uint32_t poff0 = ((wm + lrow)      * PST + lkof) * 2;
    const uint32_t poff1 = ((wm + 16 + lrow) * PST + lkof) * 2;
    const uint32_t voff = ((lane & 15) * VST + wn + lkof) * 2;

    const __half* Pb = Ph + (((size_t)(b * HH + h)) * TT + qb) * TT;
    const __half* Vb = V + ((size_t)(b * TT)) * CC + h * DD;

    auto load_stage = [&](int kt, int s) {
        #pragma unroll
        for (int i = 0; i < 2; i++) {
            int g = tid + i * 256;               // 512 P granules
            int row = g >> 2, seg = g & 3;
            CPA16(sPu + s * PSTGB + row * 80 + seg * 16,
                  Pb + (size_t)row * TT + kt * 32 + seg * 8);
        }
        {
            int row = tid >> 3, seg = tid & 7;   // 256 V granules
            CPA16(sVu + s * VSTGB + row * (VST * 2) + seg * 16,
                  Vb + (size_t)(kt * 32 + row) * CC + seg * 8);
        }
        CPCOMMIT();
    };

    load_stage(0, 0);
    load_stage(1, 1);
    load_stage(2, 2);

    float acc[2][4][4];
    #pragma unroll
    for (int i = 0; i < 2; i++)
        #pragma unroll
        for (int j = 0; j < 4; j++)
            #pragma unroll
            for (int k = 0; k < 4; k++) acc[i][j][k] = 0.f;

    const int NT2 = 32;
    for (int kt = 0; kt < NT2; kt++) {
        if (kt <= NT2 - 3)      { CPWAIT(2); }
        else if (kt == NT2 - 2) { CPWAIT(1); }
        else                    { CPWAIT(0); }
        __syncthreads();

        if (kt + 3 < NT2) load_stage(kt + 3, (kt + 3) & 3);

        const uint32_t PtU = sPu + (kt & 3) * PSTGB;
        const uint32_t VtU = sVu + (kt & 3) * VSTGB;

        #pragma unroll
        for (int ks = 0; ks < 2; ks++) {
            uint32_t af[2][4], bf[4][2];
            ldsm_x4(af[0][0], af[0][1], af[0][2], af[0][3], PtU + poff0 + ks * 32);
            ldsm_x4(af[1][0], af[1][1], af[1][2], af[1][3], PtU + poff1 + ks * 32);
            ldsm_x4t(bf[0][0], bf[0][1], bf[1][0], bf[1][1],
                     VtU + voff + ks * 16 * (VST * 2));
            ldsm_x4t(bf[2][0], bf[2][1], bf[3][0], bf[3][1],
                     VtU + voff + 16 * 2 + ks * 16 * (VST * 2));
            #pragma unroll
            for (int mt2 = 0; mt2 < 2; mt2++)
                #pragma unroll
                for (int nt = 0; nt < 4; nt++)
                    mma_f16(acc[mt2][nt], af[mt2], bf[nt]);
        }
    }

    #pragma unroll
    for (int mt2 = 0; mt2 < 2; mt2++) {
        int r0 = qb + wm + mt2 * 16 + (lane >> 2);
        #pragma unroll
        for (int nt = 0; nt < 4; nt++) {
            int c0 = wn + nt * 8 + (lane & 3) * 2;
            __half2 h01 = __floats2half2_rn(acc[mt2][nt][0], acc[mt2][nt][1]);
            __half2 h23 = __floats2half2_rn(acc[mt2][nt][2], acc[mt2][nt][3]);
            *(__half2*)&Y[(size_t)(b * TT + r0) * CC + h * DD + c0]       = h01;
            *(__half2*)&Y[(size_t)(b * TT + r0 + 8) * CC + h * DD + c0]   = h23;
        }
    }
}

// ---------------------------------------------------------------------------
// launch: prepass -> QKV proj -> scores/softmax (two-pass) -> PV -> out proj
// d_out = [ y (B*T*C) fp32 | attn (B*H*T*T) fp32 ]
// ---------------------------------------------------------------------------
extern "C" void kernel_launch(void* const* d_in, const int* in_sizes, int n_in,
                              void* d_out, int out_size)
{
    const float* x  = (const float*)d_in[0];
    const float* Wq = (const float*)d_in[1];
    const float* Wk = (const float*)d_in[2];
    const float* Wv = (const float*)d_in[3];
    const float* Wp = (const float*)d_in[4];

    float* out      = (float*)d_out;
    float* y_out    = out;
    float* attn_out = out + (size_t)BB * TT * CC;

    __half *Qh, *Kh, *Vh, *Yh, *Xh, *Wh, *Pp;
    cudaGetSymbolAddress((void**)&Qh, g_Qh);
    cudaGetSymbolAddress((void**)&Kh, g_Kh);
    cudaGetSymbolAddress((void**)&Vh, g_Vh);
    cudaGetSymbolAddress((void**)&Yh, g_Yh);
    cudaGetSymbolAddress((void**)&Xh, g_Xh);
    cudaGetSymbolAddress((void**)&Wh, g_Wh);
    cudaGetSymbolAddress((void**)&Pp, g_P);

    prepass<<<dim3(1024, 5), 256>>>(x, Wq, Wk, Wv, Wp);

    const size_t gemm_smem = (size_t)8 * GSTG;                        // 81920
    cudaFuncSetAttribute(gemm_f16_nt,
                         cudaFuncAttributeMaxDynamicSharedMemorySize,
                         (int)gemm_smem);

    dim3 gq(CC / 128, BT / 128, 3);
    gemm_f16_nt<<<gq, 512, gemm_smem>>>(Xh, Wh, Qh, Kh, Vh, nullptr, 1);

    const size_t score_smem =
        (size_t)QT * QST * 2 + 4 * KCH + (2 * 64 + 64) * sizeof(float2); // 84480
    cudaFuncSetAttribute(attn_score_kernel,
                         cudaFuncAttributeMaxDynamicSharedMemorySize,
                         (int)score_smem);
    attn_score_kernel<<<dim3(TT / QT, HH, BB), 256, score_smem>>>(
        Qh, Kh, attn_out, Pp);

    const size_t pv_smem = (size_t)4 * (PSTGB + VSTGB);               // 59392
    cudaFuncSetAttribute(pv_kernel,
                         cudaFuncAttributeMaxDynamicSharedMemorySize,
                         (int)pv_smem);
    pv_kernel<<<dim3(TT / 128, HH, BB), 256, pv_smem>>>(Pp, Vh, Yh);

    dim3 gp(CC / 128, BT / 128, 1);
    gemm_f16_nt<<<gp, 512, gemm_smem>>>(Yh, Wh + (size_t)3 * CC * CC,
                                        nullptr, nullptr, nullptr, y_out, 0);
}

// round 17
// speedup vs baseline: 1.0206x; 1.0206x over previous
#include <cuda_runtime.h>
#include <cuda_fp16.h>
#include <math.h>
#include <stdint.h>

#define BB   4
#define TT   1024
#define CC   1024
#define HH   16
#define DD   64
#define BT   (BB*TT)          // 4096

// Scratch (allocation-free rule: __device__ globals)
__device__ __half g_Qh[BT * CC];
__device__ __half g_Kh[BT * CC];
__device__ __half g_Vh[BT * CC];
__device__ __half g_Yh[BT * CC];
__device__ __half g_Xh[BT * CC];          // fp16-rounded x
__device__ __half g_Wh[4 * CC * CC];      // fp16-rounded Wq|Wk|Wv|Wp
__device__ __half g_P[(size_t)BB * HH * TT * TT];   // fp16 attention probs

// ---------------------------------------------------------------------------
// helpers
// ---------------------------------------------------------------------------
__device__ __forceinline__ uint2 f4_to_h4(float4 v) {
    __half2 a = __floats2half2_rn(v.x, v.y);
    __half2 b = __floats2half2_rn(v.z, v.w);
    uint2 r;
    r.x = *(uint32_t*)&a;
    r.y = *(uint32_t*)&b;
    return r;
}

__device__ __forceinline__ void mma_f16(float* c, const uint32_t* a, const uint32_t* b) {
    asm volatile(
        "mma.sync.aligned.m16n8k16.row.col.f32.f16.f16.f32 "
        "{%0,%1,%2,%3}, {%4,%5,%6,%7}, {%8,%9}, {%0,%1,%2,%3};"
        : "+f"(c[0]), "+f"(c[1]), "+f"(c[2]), "+f"(c[3])
        : "r"(a[0]), "r"(a[1]), "r"(a[2]), "r"(a[3]), "r"(b[0]), "r"(b[1]));
}

__device__ __forceinline__ void ldsm_x4(uint32_t& r0, uint32_t& r1,
                                        uint32_t& r2, uint32_t& r3, uint32_t addr) {
    asm volatile("ldmatrix.sync.aligned.m8n8.x4.shared.b16 {%0,%1,%2,%3}, [%4];"
                 : "=r"(r0), "=r"(r1), "=r"(r2), "=r"(r3) : "r"(addr));
}
__device__ __forceinline__ void ldsm_x4t(uint32_t& r0, uint32_t& r1,
                                         uint32_t& r2, uint32_t& r3, uint32_t addr) {
    asm volatile("ldmatrix.sync.aligned.m8n8.x4.trans.shared.b16 {%0,%1,%2,%3}, [%4];"
                 : "=r"(r0), "=r"(r1), "=r"(r2), "=r"(r3) : "r"(addr));
}

// streaming stores (write-through, no L2 allocate) for never-re-read outputs
__device__ __forceinline__ void stwt_f2(float* p, float2 v) {
    asm volatile("st.global.wt.v2.f32 [%0], {%1,%2};"
                 :: "l"(p), "f"(v.x), "f"(v.y) : "memory");
}
__device__ __forceinline__ void stwt_u1(__half* p, uint32_t v) {
    asm volatile("st.global.wt.u32 [%0], %1;"
                 :: "l"(p), "r"(v) : "memory");
}

#define CPA16(dst_u32, src_ptr) \
    asm volatile("cp.async.cg.shared.global [%0], [%1], 16;" \
                 :: "r"(dst_u32), "l"(src_ptr))
#define CPCOMMIT() asm volatile("cp.async.commit_group;")
#define CPWAIT(n)  asm volatile("cp.async.wait_group %0;" :: "n"(n))

// ---------------------------------------------------------------------------
// prepass: fp16-round x -> g_Xh, weights -> g_Wh (concat)
// ---------------------------------------------------------------------------
__global__ void prepass(const float* __restrict__ x,
                        const float* __restrict__ wq, const float* __restrict__ wk,
                        const float* __restrict__ wv, const float* __restrict__ wp)
{
    int which = blockIdx.y;
    const float* src;
    __half* dst;
    int n4;
    if (which == 0) { src = x;  dst = g_Xh; n4 = BT * CC / 4; }
    else {
        src = (which == 1) ? wq : (which == 2) ? wk : (which == 3) ? wv : wp;
        dst = g_Wh + (size_t)(which - 1) * CC * CC;
        n4 = CC * CC / 4;
    }
    for (int i = blockIdx.x * blockDim.x + threadIdx.x; i < n4;
         i += gridDim.x * blockDim.x) {
        float4 v = ((const float4*)src)[i];
        ((uint2*)dst)[i] = f4_to_h4(v);
    }
}

// ---------------------------------------------------------------------------
// C[M,N] = A[M,K] @ W[N,K]^T, FP16 MMA m16n8k16, inputs pre-rounded fp16.
// 128x128 tile, BK=32, 512 threads, 4-stage cp.async, ldmatrix fragments.
// (R7/R10 configuration — known good.)
// ---------------------------------------------------------------------------
#define AST 40                   // halfs per row (80 bytes)
#define GSTG (128 * AST * 2)     // stage bytes per array: 10240
#define NTG 32                   // K/32
__global__ __launch_bounds__(512, 1)
void gemm_f16_nt(const __half* __restrict__ A, const __half* __restrict__ Wb,
                 __half* __restrict__ H0, __half* __restrict__ H1,
                 __half* __restrict__ H2, float* __restrict__ C0, int ro)
{
    const __half* Bw = Wb + (size_t)blockIdx.z * CC * CC;
    __half* H = (blockIdx.z == 0) ? H0 : (blockIdx.z == 1 ? H1 : H2);

    extern __shared__ char smraw[];
    uint32_t sAu = (uint32_t)__cvta_generic_to_shared(smraw);
    uint32_t sBu = sAu + 4 * GSTG;

    const int tid  = threadIdx.x;
    const int lane = tid & 31;
    const int warp = tid >> 5;
    const int wm   = (warp & 3) * 32;
    const int wn   = (warp >> 2) * 32;

    const int lrow = lane & 15;
    const int lkof = (lane & 16) ? 8 : 0;     // halfs
    const uint32_t aoff0 = ((wm + lrow)      * AST + lkof) * 2;
    const uint32_t aoff1 = ((wm + 16 + lrow) * AST + lkof) * 2;
    const uint32_t boff0 = ((wn + lrow)      * AST + lkof) * 2;
    const uint32_t boff1 = ((wn + 16 + lrow) * AST + lkof) * 2;

    const __half* Abase = A  + (size_t)(blockIdx.y * 128) * CC;
    const __half* Bbase = Bw + (size_t)(blockIdx.x * 128) * CC;

    auto load_stage = [&](int kt, int s) {
        int row = tid >> 2, seg = tid & 3;               // 512 granules per array
        CPA16(sAu + s * GSTG + row * 80 + seg * 16,
              Abase + (size_t)row * CC + kt * 32 + seg * 8);
        CPA16(sBu + s * GSTG + row * 80 + seg * 16,
              Bbase + (size_t)row * CC + kt * 32 + seg * 8);
        CPCOMMIT();
    };

    load_stage(0, 0);
    load_stage(1, 1);
    load_stage(2, 2);

    float acc[2][4][4];
    #pragma unroll
    for (int i = 0; i < 2; i++)
        #pragma unroll
        for (int j = 0; j < 4; j++)
            #pragma unroll
            for (int k = 0; k < 4; k++) acc[i][j][k] = 0.f;

    for (int kt = 0; kt < NTG; kt++) {
        if (kt <= NTG - 3)      { CPWAIT(2); }
        else if (kt == NTG - 2) { CPWAIT(1); }
        else                    { CPWAIT(0); }
        __syncthreads();

        if (kt + 3 < NTG) load_stage(kt + 3, (kt + 3) & 3);

        const uint32_t AbU = sAu + (kt & 3) * GSTG;
        const uint32_t BbU = sBu + (kt & 3) * GSTG;

        #pragma unroll
        for (int ks = 0; ks < 2; ks++) {                 // 2 x k16
            uint32_t af[2][4], bf[4][2];
            ldsm_x4(af[0][0], af[0][1], af[0][2], af[0][3], AbU + aoff0 + ks * 32);
            ldsm_x4(af[1][0], af[1][1], af[1][2], af[1][3], AbU + aoff1 + ks * 32);
            ldsm_x4(bf[0][0], bf[1][0], bf[0][1], bf[1][1], BbU + boff0 + ks * 32);
            ldsm_x4(bf[2][0], bf[3][0], bf[2][1], bf[3][1], BbU + boff1 + ks * 32);
            #pragma unroll
            for (int mt = 0; mt < 2; mt++)
                #pragma unroll
                for (int nt = 0; nt < 4; nt++)
                    mma_f16(acc[mt][nt], af[mt], bf[nt]);
        }
    }

    #pragma unroll
    for (int mt = 0; mt < 2; mt++) {
        int r0 = blockIdx.y * 128 + wm + mt * 16 + (lane >> 2);
        #pragma unroll
        for (int nt = 0; nt < 4; nt++) {
            int c0 = blockIdx.x * 128 + wn + nt * 8 + (lane & 3) * 2;
            if (ro) {
                __half2 h01 = __floats2half2_rn(acc[mt][nt][0], acc[mt][nt][1]);
                __half2 h23 = __floats2half2_rn(acc[mt][nt][2], acc[mt][nt][3]);
                *(__half2*)&H[(size_t)r0 * CC + c0]       = h01;
                *(__half2*)&H[(size_t)(r0 + 8) * CC + c0] = h23;
            } else {
                stwt_f2(&C0[(size_t)r0 * CC + c0],
                        make_float2(acc[mt][nt][0], acc[mt][nt][1]));
                stwt_f2(&C0[(size_t)(r0 + 8) * CC + c0],
                        make_float2(acc[mt][nt][2], acc[mt][nt][3]));
            }
        }
    }
}

// ---------------------------------------------------------------------------
// Kernel A: two-pass strip-free scores + ALiBi + online softmax.
// block=(b,h,64q), 256 thr, 3-stage K ring -> smem 66KB -> 3 CTAs/SM (24 warps).
// Pass 1 (cc 0..7): QK chunks, online (max, rescaled exp-sum) per row.
// cc==8: combine partials -> per-row (M, 1/sum).
// Pass 2 (cc 8..15): recompute chunks (bit-identical MMAs), stream out
// normalized attn fp32 + P fp16 from fragments.
// ---------------------------------------------------------------------------
#define QT   64
#define QST  72
#define KST  72
#define KCH  (128 * KST * 2)     // 18432 bytes per K chunk buffer
__global__ __launch_bounds__(256, 3)
void attn_score_kernel(const __half* __restrict__ Q, const __half* __restrict__ Km,
                       float* __restrict__ attn, __half* __restrict__ Ph)
{
    extern __shared__ char smraw[];
    __half* sQ = (__half*)smraw;                           // 64*72 halfs (9216B)
    char*   sK = smraw + QT * QST * 2;                     // 3 * KCH (55296B)
    float2* sStat = (float2*)(smraw + QT * QST * 2 + 3 * KCH);   // [2][64]
    float2* sFin  = sStat + 2 * 64;                               // [64]
    uint32_t sQu = (uint32_t)__cvta_generic_to_shared(sQ);
    uint32_t sKu = (uint32_t)__cvta_generic_to_shared(sK);

    const int tid  = threadIdx.x;
    const int lane = tid & 31;
    const int warp = tid >> 5;            // 0..7
    const int qb   = blockIdx.x * QT;
    const int h    = blockIdx.y;
    const int b    = blockIdx.z;

    const float scale = 0.125f;
    const float slope = exp2f(-0.5f * (float)(h + 1));

    const int mt    = warp >> 1;          // m16 tile (rows mt*16..+15)
    const int nhalf = warp & 1;           // n64 half of the 128-col chunk

    const int lrow = lane & 15;
    const int lkof = (lane & 16) ? 8 : 0;

    const __half* Kb = Km + ((size_t)(b * TT)) * CC + h * DD;

    auto issueK = [&](int c, int buf) {
        const __half* base = Kb + (size_t)(c * 128) * CC;
        #pragma unroll
        for (int i = 0; i < 4; i++) {
            int g = tid + i * 256;              // 1024 granules
            int row = g >> 3, seg = g & 7;
            CPA16(sKu + buf * KCH + row * (KST * 2) + seg * 16,
                  base + (size_t)row * CC + seg * 8);
        }
        CPCOMMIT();
    };

    // 3-stage ring: prologue fills 2 slots; prefetch lag 2.
    issueK(0, 0);
    issueK(1, 1);

    // Q tile [64 x 64] halfs -> sQ
    {
        const __half* Qb = Q + ((size_t)(b * TT + qb)) * CC + h * DD;
        #pragma unroll
        for (int i = 0; i < 2; i++) {
            int g = tid + i * 256;              // 512 granules
            int row = g >> 3, seg = g & 7;
            *(uint4*)(sQ + row * QST + seg * 8) =
                *(const uint4*)(Qb + (size_t)row * CC + seg * 8);
        }
    }
    __syncthreads();

    // hoist Q fragments (this warp's m16 tile, all 4 k16 steps)
    uint32_t aq[4][4];
    {
        uint32_t qoff = sQu + ((mt * 16 + lrow) * QST + lkof) * 2;
        #pragma unroll
        for (int ks = 0; ks < 4; ks++)
            ldsm_x4(aq[ks][0], aq[ks][1], aq[ks][2], aq[ks][3], qoff + ks * 32);
    }

    uint32_t koffj[4];
    #pragma unroll
    for (int j = 0; j < 4; j++)
        koffj[j] = ((nhalf * 64 + j * 16 + lrow) * KST + lkof) * 2;

    float mrow[2] = {-1e30f, -1e30f};
    float srow[2] = {0.f, 0.f};
    float Mrow[2], Ivrow[2];

    const size_t attn_base = (((size_t)(b * HH + h)) * TT + qb) * TT;
    const int r0 = mt * 16 + (lane >> 2);
    const float q0f = (float)(qb + r0);

    int buf = 0;   // ring cursor: slot holding chunk for iteration cc
    for (int cc = 0; cc < 16; cc++) {
        if (cc < 15) { CPWAIT(1); } else { CPWAIT(0); }
        __syncthreads();   // all warps done reading the slot we're about to refill

        if (cc + 2 < 16) {
            int nb = buf + 2; if (nb >= 3) nb -= 3;
            issueK((cc + 2) & 7, nb);
        }

        if (cc == 8) {
            // finalize pass-1 stats: reduce over the 4-lane col group
            #pragma unroll
            for (int ri = 0; ri < 2; ri++) {
                float m = mrow[ri], s = srow[ri];
                #pragma unroll
                for (int off = 1; off <= 2; off <<= 1) {
                    float mo = __shfl_xor_sync(~0u, m, off);
                    float so = __shfl_xor_sync(~0u, s, off);
                    float mn = fmaxf(m, mo);
                    s = s * __expf(m - mn) + so * __expf(mo - mn);
                    m = mn;
                }
                mrow[ri] = m; srow[ri] = s;
            }
            if ((lane & 3) == 0) {
                sStat[nhalf * 64 + r0]     = make_float2(mrow[0], srow[0]);
                sStat[nhalf * 64 + r0 + 8] = make_float2(mrow[1], srow[1]);
            }
            __syncthreads();
            if (tid < 64) {
                float2 a = sStat[tid], c2 = sStat[64 + tid];
                float M = fmaxf(a.x, c2.x);
                float sum = a.y * __expf(a.x - M) + c2.y * __expf(c2.x - M);
                sFin[tid] = make_float2(M, 1.0f / sum);
            }
            __syncthreads();
            float2 f0 = sFin[r0], f1 = sFin[r0 + 8];
            Mrow[0] = f0.x; Ivrow[0] = f0.y;
            Mrow[1] = f1.x; Ivrow[1] = f1.y;
        }

        const int chunk = cc & 7;
        const uint32_t KU = sKu + buf * KCH;

        float cr[8][4];
        #pragma unroll
        for (int nt = 0; nt < 8; nt++)
            #pragma unroll
            for (int i = 0; i < 4; i++) cr[nt][i] = 0.f;

        #pragma unroll
        for (int ks = 0; ks < 4; ks++) {
            uint32_t bf[8][2];
            #pragma unroll
            for (int j = 0; j < 4; j++)
                ldsm_x4(bf[2 * j][0], bf[2 * j + 1][0],
                        bf[2 * j][1], bf[2 * j + 1][1], KU + koffj[j] + ks * 32);
            #pragma unroll
            for (int nt = 0; nt < 8; nt++)
                mma_f16(cr[nt], aq[ks], bf[nt]);
        }

        // in-place: MMA result -> ALiBi score
        const int kc = chunk * 128;
        #pragma unroll
        for (int nt = 0; nt < 8; nt++) {
            #pragma unroll
            for (int i = 0; i < 4; i++) {
                float qf = q0f + (float)((i >> 1) * 8);
                float kf = (float)(kc + nhalf * 64 + nt * 8 + (lane & 3) * 2 + (i & 1));
                cr[nt][i] = cr[nt][i] * scale - slope * fabsf(qf - kf);
            }
        }

        if (cc < 8) {
            // pass 1: online max + rescaled exp-sum per row
            #pragma unroll
            for (int ri = 0; ri < 2; ri++) {
                float vmax = -1e30f;
                #pragma unroll
                for (int nt = 0; nt < 8; nt++)
                    vmax = fmaxf(vmax, fmaxf(cr[nt][ri * 2], cr[nt][ri * 2 + 1]));
                float mn = fmaxf(mrow[ri], vmax);
                float acc = 0.f;
                #pragma unroll
                for (int nt = 0; nt < 8; nt++)
                    acc += __expf(cr[nt][ri * 2] - mn) + __expf(cr[nt][ri * 2 + 1] - mn);
                srow[ri] = srow[ri] * __expf(mrow[ri] - mn) + acc;
                mrow[ri] = mn;
            }
        } else {
            // pass 2: normalize + stream out attn fp32 and P fp16
            #pragma unroll
            for (int ri = 0; ri < 2; ri++) {
                int r = r0 + ri * 8;
                float*  orow = attn + attn_base + (size_t)r * TT;
                __half* prow = Ph + attn_base + (size_t)r * TT;
                #pragma unroll
                for (int nt = 0; nt < 8; nt++) {
                    float p0 = __expf(cr[nt][ri * 2]     - Mrow[ri]) * Ivrow[ri];
                    float p1 = __expf(cr[nt][ri * 2 + 1] - Mrow[ri]) * Ivrow[ri];
                    int col = kc + nhalf * 64 + nt * 8 + (lane & 3) * 2;
                    stwt_f2(orow + col, make_float2(p0, p1));
                    __half2 hp = __floats2half2_rn(p0, p1);
                    stwt_u1(prow + col, *(uint32_t*)&hp);
                }
            }
        }

        buf++; if (buf >= 3) buf -= 3;
    }
}

// ---------------------------------------------------------------------------
// Kernel B: Y[128x64] = P[128x1024] @ V[1024x64] per (b,h,qtile), all fp16.
// 256 thr, 4-stage cp.async, P via ldmatrix, V via ldmatrix.trans.
// (R10 configuration — known good.)
// ---------------------------------------------------------------------------
#define PST 40
#define VST 72
#define PSTGB (128 * PST * 2)     // 10240
#define VSTGB (32 * VST * 2)      // 4608
__global__ __launch_bounds__(256, 2)
void pv_kernel(const __half* __restrict__ Ph, const __half* __restrict__ V,
               __half* __restrict__ Y)
{
    extern __shared__ char smraw[];
    uint32_t sPu = (uint32_t)__cvta_generic_to_shared(smraw);
    uint32_t sVu = sPu + 4 * PSTGB;

    const int tid  = threadIdx.x;
    const int lane = tid & 31;
    const int warp = tid >> 5;            // 0..7
    const int qb   = blockIdx.x * 128;
    const int h    = blockIdx.y;
    const int b    = blockIdx.z;

    const int wm = (warp >> 1) * 32;
    const int wn = (warp & 1) * 32;

    const int lrow = lane & 15;
    const int lkof = (lane & 16) ? 8 : 0;
    const uint32_t poff0 = ((wm + lrow)      * PST + lkof) * 2;
    const uint32_t poff1 = ((wm + 16 + lrow) * PST + lkof) * 2;
    const uint32_t voff = ((lane & 15) * VST + wn + lkof) * 2;

    const __half* Pb = Ph + (((size_t)(b * HH + h)) * TT + qb) * TT;
    const __half* Vb = V + ((size_t)(b * TT)) * CC + h * DD;

    auto load_stage = [&](int kt, int s) {
        #pragma unroll
        for (int i = 0; i < 2; i++) {
            int g = tid + i * 256;               // 512 P granules
            int row = g >> 2, seg = g & 3;
            CPA16(sPu + s * PSTGB + row * 80 + seg * 16,
                  Pb + (size_t)row * TT + kt * 32 + seg * 8);
        }
        {
            int row = tid >> 3, seg = tid & 7;   // 256 V granules
            CPA16(sVu + s * VSTGB + row * (VST * 2) + seg * 16,
                  Vb + (size_t)(kt * 32 + row) * CC + seg * 8);
        }
        CPCOMMIT();
    };

    load_stage(0, 0);
    load_stage(1, 1);
    load_stage(2, 2);

    float acc[2][4][4];
    #pragma unroll
    for (int i = 0; i < 2; i++)
        #pragma unroll
        for (int j = 0; j < 4; j++)
            #pragma unroll
            for (int k = 0; k < 4; k++) acc[i][j][k] = 0.f;

    const int NT2 = 32;
    for (int kt = 0; kt < NT2; kt++) {
        if (kt <= NT2 - 3)      { CPWAIT(2); }
        else if (kt == NT2 - 2) { CPWAIT(1); }
        else                    { CPWAIT(0); }
        __syncthreads();

        if (kt + 3 < NT2) load_stage(kt + 3, (kt + 3) & 3);

        const uint32_t PtU = sPu + (kt & 3) * PSTGB;
        const uint32_t VtU = sVu + (kt & 3) * VSTGB;

        #pragma unroll
        for (int ks = 0; ks < 2; ks++) {
            uint32_t af[2][4], bf[4][2];
            ldsm_x4(af[0][0], af[0][1], af[0][2], af[0][3], PtU + poff0 + ks * 32);
            ldsm_x4(af[1][0], af[1][1], af[1][2], af[1][3], PtU + poff1 + ks * 32);
            ldsm_x4t(bf[0][0], bf[0][1], bf[1][0], bf[1][1],
                     VtU + voff + ks * 16 * (VST * 2));
            ldsm_x4t(bf[2][0], bf[2][1], bf[3][0], bf[3][1],
                     VtU + voff + 16 * 2 + ks * 16 * (VST * 2));
            #pragma unroll
            for (int mt2 = 0; mt2 < 2; mt2++)
                #pragma unroll
                for (int nt = 0; nt < 4; nt++)
                    mma_f16(acc[mt2][nt], af[mt2], bf[nt]);
        }
    }

    #pragma unroll
    for (int mt2 = 0; mt2 < 2; mt2++) {
        int r0 = qb + wm + mt2 * 16 + (lane >> 2);
        #pragma unroll
        for (int nt = 0; nt < 4; nt++) {
            int c0 = wn + nt * 8 + (lane & 3) * 2;
            __half2 h01 = __floats2half2_rn(acc[mt2][nt][0], acc[mt2][nt][1]);
            __half2 h23 = __floats2half2_rn(acc[mt2][nt][2], acc[mt2][nt][3]);
            *(__half2*)&Y[(size_t)(b * TT + r0) * CC + h * DD + c0]       = h01;
            *(__half2*)&Y[(size_t)(b * TT + r0 + 8) * CC + h * DD + c0]   = h23;
        }
    }
}

// ---------------------------------------------------------------------------
// launch: prepass -> QKV proj -> scores/softmax (two-pass, occ3) -> PV -> out
// d_out = [ y (B*T*C) fp32 | attn (B*H*T*T) fp32 ]
// ---------------------------------------------------------------------------
extern "C" void kernel_launch(void* const* d_in, const int* in_sizes, int n_in,
                              void* d_out, int out_size)
{
    const float* x  = (const float*)d_in[0];
    const float* Wq = (const float*)d_in[1];
    const float* Wk = (const float*)d_in[2];
    const float* Wv = (const float*)d_in[3];
    const float* Wp = (const float*)d_in[4];

    float* out      = (float*)d_out;
    float* y_out    = out;
    float* attn_out = out + (size_t)BB * TT * CC;

    __half *Qh, *Kh, *Vh, *Yh, *Xh, *Wh, *Pp;
    cudaGetSymbolAddress((void**)&Qh, g_Qh);
    cudaGetSymbolAddress((void**)&Kh, g_Kh);
    cudaGetSymbolAddress((void**)&Vh, g_Vh);
    cudaGetSymbolAddress((void**)&Yh, g_Yh);
    cudaGetSymbolAddress((void**)&Xh, g_Xh);
    cudaGetSymbolAddress((void**)&Wh, g_Wh);
    cudaGetSymbolAddress((void**)&Pp, g_P);

    prepass<<<dim3(1024, 5), 256>>>(x, Wq, Wk, Wv, Wp);

    const size_t gemm_smem = (size_t)8 * GSTG;                        // 81920
    cudaFuncSetAttribute(gemm_f16_nt,
                         cudaFuncAttributeMaxDynamicSharedMemorySize,
                         (int)gemm_smem);

    dim3 gq(CC / 128, BT / 128, 3);
    gemm_f16_nt<<<gq, 512, gemm_smem>>>(Xh, Wh, Qh, Kh, Vh, nullptr, 1);

    const size_t score_smem =
        (size_t)QT * QST * 2 + 3 * KCH + (2 * 64 + 64) * sizeof(float2); // 66048
    cudaFuncSetAttribute(attn_score_kernel,
                         cudaFuncAttributeMaxDynamicSharedMemorySize,
                         (int)score_smem);
    attn_score_kernel<<<dim3(TT / QT, HH, BB), 256, score_smem>>>(
        Qh, Kh, attn_out, Pp);

    const size_t pv_smem = (size_t)4 * (PSTGB + VSTGB);               // 59392
    cudaFuncSetAttribute(pv_kernel,
                         cudaFuncAttributeMaxDynamicSharedMemorySize,
                         (int)pv_smem);
    pv_kernel<<<dim3(TT / 128, HH, BB), 256, pv_smem>>>(Pp, Vh, Yh);

    dim3 gp(CC / 128, BT / 128, 1);
    gemm_f16_nt<<<gp, 512, gemm_smem>>>(Yh, Wh + (size_t)3 * CC * CC,
                                        nullptr, nullptr, nullptr, y_out, 0);
}